// round 16
// baseline (speedup 1.0000x reference)
#include <cuda_runtime.h>
#include <cuda_fp16.h>
#include <cstdint>
#include <float.h>

#define NTOK 32768
#define DIMD 256
#define KVOC 8192
#define NTIL   64           // n-tiles of 128 codewords
#define MGRP   8            // m-tiles per CTA (persistent-B coarse gemm)
#define TAU  0.02f
#define KSPL 768            // split-K: [x_hi|x_lo|x_hi] . [v_hi|v_hi|v_lo]

// ---- device scratch ----
__device__ __half g_Ah[(size_t)NTOK * DIMD];   // 16 MB fp16 tokens (coarse)
__device__ __half g_Bh[(size_t)KVOC * DIMD];   // 4 MB fp16 vocab (coarse)
__device__ __half g_As[(size_t)NTOK * KSPL];   // split-A (flagged, compact)
__device__ __half g_Bs[(size_t)KVOC * KSPL];   // split-B
__device__ float  g_vnorm[KVOC];               // 0.5*||v||^2 fp32
__device__ float  g_s1[(size_t)NTIL * NTOK];
__device__ float  g_s2[(size_t)NTIL * NTOK];
__device__ int    g_i1[(size_t)NTIL * NTOK];
__device__ unsigned long long g_key[NTOK];
__device__ int    g_wl[NTOK];
__device__ int    g_wlcount;

// ---- coarse gemm smem: A stages (2x16KB) | B chunks (4x16KB) | vn ----
#define SA_OFF(st) ((st) * 16384)
#define SB_OFF(c)  (32768 + (c) * 16384)
#define SO_VN  98304
#define SM_TOTAL 98816

// ---- cleanup gemm smem (64x64 tile): 2 stages x (A 8KB + B 8KB) | vn | red | tk ----
#define CU_ST(st)  ((st) * 16384)
#define CU_VN  32768
#define CU_R1  33024
#define CU_RI  34048
#define CU_TK  35072
#define CU_SM_TOTAL 35328

// ============================ asm helpers ============================
__device__ __forceinline__ uint32_t smem_u32(const void* p) {
    uint32_t a;
    asm("{ .reg .u64 t; cvta.to.shared.u64 t, %1; cvt.u32.u64 %0, t; }"
        : "=r"(a) : "l"(p));
    return a;
}
__device__ __forceinline__ void cpasync16(uint32_t s, const void* g) {
    asm volatile("cp.async.cg.shared.global [%0], [%1], 16;" :: "r"(s), "l"(g));
}
#define CP_COMMIT() asm volatile("cp.async.commit_group;" ::: "memory")
#define CP_WAIT(N)  asm volatile("cp.async.wait_group " #N ";" ::: "memory")

__device__ __forceinline__ void ldsm4(uint32_t& r0, uint32_t& r1, uint32_t& r2,
                                      uint32_t& r3, uint32_t addr) {
    asm volatile("ldmatrix.sync.aligned.m8n8.x4.shared.b16 {%0,%1,%2,%3}, [%4];"
                 : "=r"(r0), "=r"(r1), "=r"(r2), "=r"(r3) : "r"(addr));
}
__device__ __forceinline__ void mma16816(float* d, const uint32_t* a,
                                         uint32_t b0, uint32_t b1) {
    asm volatile(
        "mma.sync.aligned.m16n8k16.row.col.f32.f16.f16.f32 "
        "{%0,%1,%2,%3},{%4,%5,%6,%7},{%8,%9},{%0,%1,%2,%3};"
        : "+f"(d[0]), "+f"(d[1]), "+f"(d[2]), "+f"(d[3])
        : "r"(a[0]), "r"(a[1]), "r"(a[2]), "r"(a[3]), "r"(b0), "r"(b1));
}
__device__ __forceinline__ uint32_t swz(uint32_t off) {
    return off ^ ((off >> 3) & 0x70);
}
__device__ __forceinline__ uint32_t f2ord(float s) {
    uint32_t fb = __float_as_uint(s);
    return (fb & 0x80000000u) ? ~fb : (fb | 0x80000000u);
}

// =================== convert kernel (seq fp16 + vocab fp16/vnorm) ===================
__global__ void convert_kernel(const float* __restrict__ seq,
                               const float* __restrict__ vocab) {
    if (blockIdx.x == 0 && threadIdx.x == 0) g_wlcount = 0;
    if (blockIdx.x < 2048) {
        int gid = blockIdx.x * 256 + threadIdx.x;     // 524288 threads
        const float4* s4 = (const float4*)seq + (size_t)gid * 4;
        uint2 u[4];
        #pragma unroll
        for (int k = 0; k < 4; k++) {
            float4 x = s4[k];
            __half2 a = __floats2half2_rn(x.x, x.y);
            __half2 b = __floats2half2_rn(x.z, x.w);
            u[k].x = *(uint32_t*)&a; u[k].y = *(uint32_t*)&b;
        }
        uint4* dst = (uint4*)(g_Ah + (size_t)gid * 16);
        dst[0] = make_uint4(u[0].x, u[0].y, u[1].x, u[1].y);
        dst[1] = make_uint4(u[2].x, u[2].y, u[3].x, u[3].y);
    } else {
        int row  = (blockIdx.x - 2048) * 8 + (threadIdx.x >> 5);
        int lane = threadIdx.x & 31;
        const float4* v = (const float4*)(vocab + (size_t)row * DIMD);
        float s = 0.f;
        #pragma unroll
        for (int c4 = lane; c4 < 64; c4 += 32) {
            float4 x = v[c4];
            s += x.x*x.x + x.y*x.y + x.z*x.z + x.w*x.w;
            __half2 a = __floats2half2_rn(x.x, x.y);
            __half2 b = __floats2half2_rn(x.z, x.w);
            uint2 u;
            u.x = *(uint32_t*)&a; u.y = *(uint32_t*)&b;
            *(uint2*)(g_Bh + (size_t)row * DIMD + c4 * 4) = u;
        }
        #pragma unroll
        for (int o = 16; o; o >>= 1) s += __shfl_xor_sync(0xffffffffu, s, o);
        if (lane == 0) g_vnorm[row] = 0.5f * s;
    }
}

// ====== persistent-B fp16 coarse GEMM, row-owning warps, fused top-2 ======
// Also builds split-B (g_Bs) in its tail: 2048 CTAs x 4 vocab rows.
__global__ __launch_bounds__(256, 2)
void gemm_kernel(const float* __restrict__ vocab) {
    extern __shared__ char smem[];
    uint32_t sbase = smem_u32(smem);
    float* s_vn = (float*)(smem + SO_VN);

    const int tid = threadIdx.x, lane = tid & 31, wid = tid >> 5;
    const int bn = blockIdx.x & (NTIL - 1);         // n-tile
    const int mg = blockIdx.x >> 6;                 // m-group
    const int n0 = bn * 128;
    const int mbase = mg * MGRP * 128;

    const char* Bb = (const char*)g_Bh + (size_t)n0 * 512;

    // ---- B n-tile (64KB = 4 chunk sub-tiles), one group
    #pragma unroll
    for (int q = 0; q < 16; q++) {
        int c  = q >> 2;
        int p  = tid + 256 * (q & 3);
        int r  = p >> 3, jj = p & 7;
        cpasync16(sbase + SB_OFF(c) + swz(r * 128 + jj * 16),
                  Bb + (size_t)r * 512 + c * 128 + jj * 16);
    }
    CP_COMMIT();

    // A chunk J (J = mt*4 + c) -> stage (J & 1)
#define LOAD_A(J)                                                              \
    {                                                                          \
        uint32_t st = sbase + SA_OFF((J) & 1);                                 \
        const char* Asrc = (const char*)g_Ah                                   \
            + (size_t)(mbase + ((J) >> 2) * 128) * 512 + ((J) & 3) * 128;      \
        _Pragma("unroll")                                                      \
        for (int q = 0; q < 4; q++) {                                          \
            int p = tid + 256 * q; int r = p >> 3, jj = p & 7;                 \
            cpasync16(st + swz(r * 128 + jj * 16),                             \
                      Asrc + (size_t)r * 512 + jj * 16);                       \
        }                                                                      \
        CP_COMMIT();                                                           \
    }

    LOAD_A(0)
    if (tid < 128) s_vn[tid] = g_vnorm[n0 + tid];

    // warp wid owns rows [wid*16, wid*16+16) x all 128 cols
    float acc[16][4];

    for (int mt = 0; mt < MGRP; mt++) {
        #pragma unroll
        for (int g = 0; g < 16; g++)
            #pragma unroll
            for (int c = 0; c < 4; c++) acc[g][c] = 0.f;

        #pragma unroll
        for (int c = 0; c < 4; c++) {
            const int j = mt * 4 + c;
            CP_WAIT(0);
            __syncthreads();            // chunk j ready; stage (j+1)&1 free
            if (j + 1 < MGRP * 4) LOAD_A(j + 1)

            uint32_t Abase = sbase + SA_OFF(j & 1);
            uint32_t Bbase = sbase + SB_OFF(c);
            #pragma unroll
            for (int ks = 0; ks < 4; ks++) {
                uint32_t af[4];
                {
                    int row = wid * 16 + (lane & 15);
                    uint32_t ad = Abase + swz(row * 128 + ks * 32 + (lane >> 4) * 16);
                    ldsm4(af[0], af[1], af[2], af[3], ad);
                }
                uint32_t bf[8][4];
                #pragma unroll
                for (int nb = 0; nb < 8; nb++) {
                    int row = nb * 16 + (lane & 15);
                    uint32_t bd = Bbase + swz(row * 128 + ks * 32 + (lane >> 4) * 16);
                    ldsm4(bf[nb][0], bf[nb][1], bf[nb][2], bf[nb][3], bd);
                }
                #pragma unroll
                for (int nb = 0; nb < 8; nb++) {
                    mma16816(acc[nb * 2],     af, bf[nb][0], bf[nb][2]);
                    mma16816(acc[nb * 2 + 1], af, bf[nb][1], bf[nb][3]);
                }
            }
        }

        // ---- warp-local top-2 epilogue (no smem, no barriers) ----
        const int m0 = mbase + mt * 128;
        float m1[2] = {FLT_MAX, FLT_MAX}, m2[2] = {FLT_MAX, FLT_MAX};
        int   i1[2] = {0x7FFFFFFF, 0x7FFFFFFF};

        #pragma unroll
        for (int g = 0; g < 16; g++) {
            int nb_ = g * 8 + (lane & 3) * 2;
            float vn0 = s_vn[nb_], vn1 = s_vn[nb_ + 1];
            #pragma unroll
            for (int c = 0; c < 4; c++) {
                int sl = c >> 1;
                float sc = ((c & 1) ? vn1 : vn0) - acc[g][c];
                int n = n0 + nb_ + (c & 1);
                if (sc < m1[sl]) { m2[sl] = m1[sl]; m1[sl] = sc; i1[sl] = n; }
                else if (sc < m2[sl]) m2[sl] = sc;
            }
        }
        #pragma unroll
        for (int off = 1; off <= 2; off <<= 1) {
            #pragma unroll
            for (int sl = 0; sl < 2; sl++) {
                float om1 = __shfl_xor_sync(0xffffffffu, m1[sl], off);
                float om2 = __shfl_xor_sync(0xffffffffu, m2[sl], off);
                int   oi  = __shfl_xor_sync(0xffffffffu, i1[sl], off);
                if (om1 < m1[sl] || (om1 == m1[sl] && oi < i1[sl])) {
                    m2[sl] = fminf(m1[sl], om2); m1[sl] = om1; i1[sl] = oi;
                } else {
                    m2[sl] = fminf(m2[sl], om1);
                }
            }
        }
        // redistribute so lanes 0..15 hold token wid*16+lane -> coalesced stores
        {
            int src = (lane & 7) * 4;           // quad leader for (lane mod 8)
            float a1 = __shfl_sync(0xffffffffu, m1[0], src);
            float b1 = __shfl_sync(0xffffffffu, m1[1], src);
            float a2 = __shfl_sync(0xffffffffu, m2[0], src);
            float b2 = __shfl_sync(0xffffffffu, m2[1], src);
            int   ai = __shfl_sync(0xffffffffu, i1[0], src);
            int   bi = __shfl_sync(0xffffffffu, i1[1], src);
            if (lane < 16) {
                bool hi = lane >= 8;
                int token = m0 + wid * 16 + lane;
                size_t o = (size_t)bn * NTOK + token;
                g_s1[o] = hi ? b1 : a1;
                g_s2[o] = hi ? b2 : a2;
                g_i1[o] = hi ? bi : ai;
            }
        }
    }
#undef LOAD_A

    // ---- tail: build split-B rows [blockIdx.x*4, +4) (tensor pipe idle) ----
    {
        int row  = blockIdx.x * 4 + (wid >> 1);       // 2 warps per row
        int c4   = (wid & 1) * 32 + lane;             // float4 index 0..63
        float4 x = ((const float4*)vocab)[(size_t)row * 64 + c4];
        float xs[4] = {x.x, x.y, x.z, x.w};
        __half h[4], l[4];
        #pragma unroll
        for (int i = 0; i < 4; i++) {
            h[i] = __float2half_rn(xs[i]);
            l[i] = __float2half_rn(xs[i] - __half2float(h[i]));
        }
        uint2 uh, ul;
        __half2 h0 = {h[0], h[1]}, h1 = {h[2], h[3]};
        __half2 l0 = {l[0], l[1]}, l1 = {l[2], l[3]};
        uh.x = *(uint32_t*)&h0; uh.y = *(uint32_t*)&h1;
        ul.x = *(uint32_t*)&l0; ul.y = *(uint32_t*)&l1;
        __half* rs = g_Bs + (size_t)row * KSPL;
        int col = c4 * 4;
        *(uint2*)(rs + col)       = uh;               // hi
        *(uint2*)(rs + 256 + col) = uh;               // hi
        *(uint2*)(rs + 512 + col) = ul;               // lo
    }
}

// ======== reduce + flag + inline split-A fill (2 threads/token) ========
__global__ void reduce_kernel(const float* __restrict__ seq) {
    int gid  = blockIdx.x * blockDim.x + threadIdx.x;   // 65536 threads
    int t    = gid >> 1;
    int half = gid & 1;
    int lane = threadIdx.x & 31;
    float m1 = FLT_MAX, m2 = FLT_MAX; int i1 = 0x7FFFFFFF;
    #pragma unroll 4
    for (int nt = half; nt < NTIL; nt += 2) {
        float s1 = g_s1[(size_t)nt * NTOK + t];
        float s2 = g_s2[(size_t)nt * NTOK + t];
        int   ii = g_i1[(size_t)nt * NTOK + t];
        if (s1 < m1 || (s1 == m1 && ii < i1)) {
            m2 = fminf(m1, s2); m1 = s1; i1 = ii;
        } else {
            m2 = fminf(m2, s1);
        }
    }
    // merge partner (same token, other half)
    float om1 = __shfl_xor_sync(0xffffffffu, m1, 1);
    float om2 = __shfl_xor_sync(0xffffffffu, m2, 1);
    int   oi  = __shfl_xor_sync(0xffffffffu, i1, 1);
    if (om1 < m1 || (om1 == m1 && oi < i1)) {
        m2 = fminf(m1, om2); m1 = om1; i1 = oi;
    } else {
        m2 = fminf(m2, om1);
    }
    bool flag = (m2 - m1 < TAU);
    int slot = -1;
    if (half == 0) {
        if (flag) {
            g_key[t] = 0xFFFFFFFFFFFFFFFFull;   // sentinel: exact pass decides
            slot = atomicAdd(&g_wlcount, 1);
            g_wl[slot] = t;
        } else {
            g_key[t] = ((unsigned long long)f2ord(m1) << 32) | (uint32_t)i1;
        }
    }
    // broadcast slot from the half==0 partner
    slot = __shfl_sync(0xffffffffu, slot, lane & ~1);
    if (flag) {
        // this thread fills cols [half*128, half*128+128) of split-A row `slot`
        __half* r = g_As + (size_t)slot * KSPL;
        const float4* src = (const float4*)(seq) + (size_t)t * 64 + half * 32;
        #pragma unroll 8
        for (int i = 0; i < 32; i++) {
            float4 x = src[i];
            float xs[4] = {x.x, x.y, x.z, x.w};
            __half h[4], l[4];
            #pragma unroll
            for (int k = 0; k < 4; k++) {
                h[k] = __float2half_rn(xs[k]);
                l[k] = __float2half_rn(xs[k] - __half2float(h[k]));
            }
            uint2 uh, ul;
            __half2 h0 = {h[0], h[1]}, h1 = {h[2], h[3]};
            __half2 l0 = {l[0], l[1]}, l1 = {l[2], l[3]};
            uh.x = *(uint32_t*)&h0; uh.y = *(uint32_t*)&h1;
            ul.x = *(uint32_t*)&l0; ul.y = *(uint32_t*)&l1;
            int col = half * 128 + i * 4;
            *(uint2*)(r + col)       = uh;      // hi
            *(uint2*)(r + 256 + col) = ul;      // lo
            *(uint2*)(r + 512 + col) = uh;      // hi
        }
    }
}

// ===== exact cleanup: split-fp16 GEMM (K=768), 64x64 tile, persistent =====
__global__ __launch_bounds__(256, 3)
void cleanup_gemm() {
    const int nf = g_wlcount;
    if (nf == 0) return;
    const int ngrp   = (nf + 63) >> 6;
    const int nitems = ngrp * 128;              // 128 n-slices of 64 codewords

    extern __shared__ char smem[];
    uint32_t sbase = smem_u32(smem);
    float* s_vn = (float*)(smem + CU_VN);
    float* r1a  = (float*)(smem + CU_R1);
    int*   ria  = (int*)  (smem + CU_RI);
    int*   tk   = (int*)  (smem + CU_TK);

    const int tid = threadIdx.x, lane = tid & 31, wid = tid >> 5;
    const int wm = wid & 1, wn = wid >> 1;       // wm: 32-row half, wn: 16-col group

    for (int item = blockIdx.x; item < nitems; item += gridDim.x) {
        const int mg = item >> 7;
        const int bn = item & 127;
        const int n0 = bn * 64;
        const int m0 = mg * 64;

        const char* Ab = (const char*)g_As + (size_t)m0 * (KSPL * 2);
        const char* Bb = (const char*)g_Bs + (size_t)n0 * (KSPL * 2);

        // chunk J: A 64x128B (8KB) at +0, B 64x128B (8KB) at +4096... (both 2 ops/thread)
#define CU_LOAD(J)                                                             \
        {                                                                      \
            uint32_t st = sbase + CU_ST((J) & 1);                              \
            _Pragma("unroll")                                                  \
            for (int q = 0; q < 2; q++) {                                      \
                int p = tid + 256 * q; int r = p >> 3, jj = p & 7;             \
                cpasync16(st + swz(r * 128 + jj * 16),                         \
                          Ab + (size_t)r * (KSPL * 2) + (J) * 128 + jj * 16);  \
            }                                                                  \
            _Pragma("unroll")                                                  \
            for (int q = 0; q < 2; q++) {                                      \
                int p = tid + 256 * q; int r = p >> 3, jj = p & 7;             \
                cpasync16(st + 8192 + swz(r * 128 + jj * 16),                  \
                          Bb + (size_t)r * (KSPL * 2) + (J) * 128 + jj * 16);  \
            }                                                                  \
            CP_COMMIT();                                                       \
        }

        __syncthreads();            // protect smem (tk/vn/red) across items
        CU_LOAD(0)
        CU_LOAD(1)
        if (tid < 64) {
            s_vn[tid] = g_vnorm[n0 + tid];
            int w = m0 + tid;
            tk[tid] = g_wl[w < nf ? w : (nf - 1)];
        }

        float acc[2][2][4];
        #pragma unroll
        for (int i = 0; i < 2; i++)
            #pragma unroll
            for (int j = 0; j < 2; j++)
                #pragma unroll
                for (int c = 0; c < 4; c++) acc[i][j][c] = 0.f;

#define CU_COMPUTE(ST)                                                         \
        {                                                                      \
            uint32_t Abase = sbase + CU_ST(ST);                                \
            uint32_t Bbase = Abase + 8192;                                     \
            _Pragma("unroll")                                                  \
            for (int ks = 0; ks < 4; ks++) {                                   \
                uint32_t af[2][4];                                             \
                _Pragma("unroll")                                              \
                for (int mt = 0; mt < 2; mt++) {                               \
                    int row = wm * 32 + mt * 16 + (lane & 15);                 \
                    uint32_t ad = Abase + swz(row * 128 + ks * 32 + (lane >> 4) * 16); \
                    ldsm4(af[mt][0], af[mt][1], af[mt][2], af[mt][3], ad);     \
                }                                                              \
                uint32_t bf[4];                                                \
                {                                                              \
                    int row = wn * 16 + (lane & 15);                           \
                    uint32_t bd = Bbase + swz(row * 128 + ks * 32 + (lane >> 4) * 16); \
                    ldsm4(bf[0], bf[1], bf[2], bf[3], bd);                     \
                }                                                              \
                _Pragma("unroll")                                              \
                for (int mt = 0; mt < 2; mt++) {                               \
                    mma16816(acc[mt][0], af[mt], bf[0], bf[2]);                \
                    mma16816(acc[mt][1], af[mt], bf[1], bf[3]);                \
                }                                                              \
            }                                                                  \
        }

        #pragma unroll
        for (int c = 0; c < 12; c++) {
            if (c == 11) { CP_WAIT(0); } else { CP_WAIT(1); }
            __syncthreads();
            CU_COMPUTE(c & 1)
            __syncthreads();
            if (c + 2 < 12) CU_LOAD(c + 2)
        }
#undef CU_COMPUTE
#undef CU_LOAD

        // ---- top-1 epilogue (64 rows x 64 cols) ----
        float m1[4]; int i1[4];                  // slot = mt*2 + rg
        #pragma unroll
        for (int s = 0; s < 4; s++) { m1[s] = FLT_MAX; i1[s] = 0x7FFFFFFF; }

        #pragma unroll
        for (int nt = 0; nt < 2; nt++) {
            int nloc_base = wn * 16 + nt * 8 + (lane & 3) * 2;
            #pragma unroll
            for (int cc = 0; cc < 2; cc++) {
                int nloc = nloc_base + cc;
                float vn = s_vn[nloc];
                int n = n0 + nloc;
                #pragma unroll
                for (int mt = 0; mt < 2; mt++) {
                    #pragma unroll
                    for (int rg = 0; rg < 2; rg++) {
                        int s_ = mt * 2 + rg;
                        float sc = vn - acc[mt][nt][rg * 2 + cc];
                        if (sc < m1[s_]) { m1[s_] = sc; i1[s_] = n; }
                    }
                }
            }
        }
        #pragma unroll
        for (int s = 0; s < 4; s++) {
            #pragma unroll
            for (int off = 1; off <= 2; off <<= 1) {
                float om1 = __shfl_xor_sync(0xffffffffu, m1[s], off);
                int   oi  = __shfl_xor_sync(0xffffffffu, i1[s], off);
                if (om1 < m1[s] || (om1 == m1[s] && oi < i1[s])) {
                    m1[s] = om1; i1[s] = oi;
                }
            }
        }
        if ((lane & 3) == 0) {
            #pragma unroll
            for (int mt = 0; mt < 2; mt++)
                #pragma unroll
                for (int rg = 0; rg < 2; rg++) {
                    int s_ = mt * 2 + rg;
                    int row = wm * 32 + mt * 16 + rg * 8 + (lane >> 2);
                    r1a[row * 4 + wn] = m1[s_];
                    ria[row * 4 + wn] = i1[s_];
                }
        }
        __syncthreads();
        if (tid < 64 && m0 + tid < nf) {
            float M1 = FLT_MAX; int I1 = 0x7FFFFFFF;
            #pragma unroll
            for (int w = 0; w < 4; w++) {
                float a1 = r1a[tid * 4 + w];
                int   ai = ria[tid * 4 + w];
                if (a1 < M1 || (a1 == M1 && ai < I1)) { M1 = a1; I1 = ai; }
            }
            unsigned long long key =
                ((unsigned long long)f2ord(M1) << 32) | (uint32_t)I1;
            atomicMin(&g_key[tk[tid]], key);
        }
    }
}

// ============================ gather (reads packed key) ============================
__global__ void gather_kernel(const float* __restrict__ vocab,
                              float* __restrict__ out, int write_idx) {
    int token = blockIdx.x * 4 + (threadIdx.x >> 6);
    int l     = threadIdx.x & 63;
    int idx   = (int)(unsigned)(g_key[token] & 0xFFFFFFFFull);
    const float4* src = (const float4*)(vocab + (size_t)idx * DIMD);
    float4*       dst = (float4*)(out + (size_t)token * DIMD);
    dst[l] = src[l];
    if (write_idx && l == 0)
        out[(size_t)NTOK * DIMD + token] = (float)idx;
}

// ============================ launch ============================
extern "C" void kernel_launch(void* const* d_in, const int* in_sizes, int n_in,
                              void* d_out, int out_size) {
    const float* seq   = (const float*)d_in[0];
    const float* vocab = (const float*)d_in[1];
    float* out = (float*)d_out;
    int write_idx = (out_size >= NTOK * DIMD + NTOK) ? 1 : 0;

    cudaFuncSetAttribute(gemm_kernel,
                         cudaFuncAttributeMaxDynamicSharedMemorySize, SM_TOTAL);
    cudaFuncSetAttribute(cleanup_gemm,
                         cudaFuncAttributeMaxDynamicSharedMemorySize, CU_SM_TOTAL);

    convert_kernel<<<2048 + 1024, 256>>>(seq, vocab);
    gemm_kernel<<<(NTOK / (MGRP * 128)) * NTIL, 256, SM_TOTAL>>>(vocab);
    reduce_kernel<<<NTOK * 2 / 256, 256>>>(seq);
    cleanup_gemm<<<1332, 256, CU_SM_TOTAL>>>();
    gather_kernel<<<NTOK / 4, 256>>>(vocab, out, write_idx);
}